// round 6
// baseline (speedup 1.0000x reference)
#include <cuda_runtime.h>
#include <cuda_bf16.h>
#include <mma.h>
#include <math.h>

using namespace nvcuda;

// ---------------- problem constants ----------------
#define NL 2          // layers
#define NB 4          // batch
#define NT 64         // time
#define ND 512        // input dim
#define NH 512        // hidden/proj dim
#define NC 4096       // cell dim
#define NG (4*NC)     // 16384 gate rows per dir
#define CLIPV 3.0f
#define NBLK 512      // persistent grid (<= 148*4 co-resident at 256 thr / <=64 regs)

// ---------------- device scratch (static allocation: allowed) ----------------
__device__ __align__(16) float g_pi[(size_t)2 * NB * NT * NG];   // [dir][b][t][g]  32 MiB
__device__ __align__(16) float g_x [(size_t)2 * NB * NT * NH];   // layer input  [dir][b][t][i]
__device__ __align__(16) float g_y [(size_t)2 * NB * NT * NH];   // layer raw out [dir][b][t][i]
__device__ __align__(16) float g_s [(size_t)2 * NB * NC];        // sigma(o)*tanh(c_new)
__device__ __align__(16) float g_h [(size_t)2 * NB * NH];        // hidden state

// software grid barrier state (zero-init; counter self-resets, epoch monotonic)
__device__ unsigned g_bar_cnt = 0;
__device__ volatile unsigned g_bar_epoch = 0;

__device__ __forceinline__ void grid_barrier() {
    __syncthreads();
    if (threadIdx.x == 0) {
        unsigned e = g_bar_epoch;
        __threadfence();                       // release prior writes
        if (atomicAdd(&g_bar_cnt, 1u) == NBLK - 1u) {
            g_bar_cnt = 0;
            __threadfence();                   // order reset before epoch bump
            g_bar_epoch = e + 1u;
        } else {
            while (g_bar_epoch == e) {}
            __threadfence();                   // acquire
        }
    }
    __syncthreads();
}

__device__ __forceinline__ float dot4(float4 a, float4 b) {
    return a.x*b.x + a.y*b.y + a.z*b.z + a.w*b.w;
}
__device__ __forceinline__ float sigmoidf_(float x) { return 1.0f / (1.0f + expf(-x)); }
__device__ __forceinline__ float clip3(float x)     { return fminf(CLIPV, fmaxf(-CLIPV, x)); }

// ---------------- pi GEMM: pi[d][m][n] = A[m,:] . Wi[n,:]  (split-bf16, 3 MMAs) ----
__global__ void __launch_bounds__(256)
pi_kernel(const float* __restrict__ x0, const float* __restrict__ Wi_l, int l)
{
    const int d = blockIdx.z;
    const float* A  = l ? (g_x + (size_t)d * (NB * NT * NH)) : x0;
    const float* Bg = Wi_l + (size_t)d * NG * ND;
    const int mBase = blockIdx.y * 128;
    const int nBase = blockIdx.x * 64;

    __shared__ __nv_bfloat16 As[2][128][40];
    __shared__ __nv_bfloat16 Bs[2][64][40];

    wmma::fragment<wmma::accumulator, 16, 16, 16, float> acc[2][2];
#pragma unroll
    for (int i = 0; i < 2; i++)
#pragma unroll
        for (int j = 0; j < 2; j++) wmma::fill_fragment(acc[i][j], 0.0f);

    const int w  = threadIdx.x >> 5;
    const int wm = w >> 1;
    const int wn = w & 1;

    for (int kk = 0; kk < 16; kk++) {
        const int k0 = kk * 32;
#pragma unroll
        for (int rpt = 0; rpt < 4; rpt++) {
            int id = threadIdx.x + rpt * 256;
            int r = id >> 3, c = (id & 7) << 2;
            float4 v = *(const float4*)(A + (size_t)(mBase + r) * ND + k0 + c);
            float vs[4] = {v.x, v.y, v.z, v.w};
#pragma unroll
            for (int q = 0; q < 4; q++) {
                __nv_bfloat16 hi = __float2bfloat16(vs[q]);
                As[0][r][c + q] = hi;
                As[1][r][c + q] = __float2bfloat16(vs[q] - __bfloat162float(hi));
            }
        }
#pragma unroll
        for (int rpt = 0; rpt < 2; rpt++) {
            int id = threadIdx.x + rpt * 256;
            int r = id >> 3, c = (id & 7) << 2;
            float4 v = *(const float4*)(Bg + (size_t)(nBase + r) * ND + k0 + c);
            float vs[4] = {v.x, v.y, v.z, v.w};
#pragma unroll
            for (int q = 0; q < 4; q++) {
                __nv_bfloat16 hi = __float2bfloat16(vs[q]);
                Bs[0][r][c + q] = hi;
                Bs[1][r][c + q] = __float2bfloat16(vs[q] - __bfloat162float(hi));
            }
        }
        __syncthreads();

#pragma unroll
        for (int ks = 0; ks < 2; ks++) {
            wmma::fragment<wmma::matrix_a, 16, 16, 16, __nv_bfloat16, wmma::row_major> ah[2], al[2];
            wmma::fragment<wmma::matrix_b, 16, 16, 16, __nv_bfloat16, wmma::col_major> bh[2], bl[2];
#pragma unroll
            for (int i = 0; i < 2; i++) {
                wmma::load_matrix_sync(ah[i], &As[0][wm * 32 + i * 16][ks * 16], 40);
                wmma::load_matrix_sync(al[i], &As[1][wm * 32 + i * 16][ks * 16], 40);
            }
#pragma unroll
            for (int j = 0; j < 2; j++) {
                wmma::load_matrix_sync(bh[j], &Bs[0][wn * 32 + j * 16][ks * 16], 40);
                wmma::load_matrix_sync(bl[j], &Bs[1][wn * 32 + j * 16][ks * 16], 40);
            }
#pragma unroll
            for (int i = 0; i < 2; i++)
#pragma unroll
                for (int j = 0; j < 2; j++) {
                    wmma::mma_sync(acc[i][j], ah[i], bh[j], acc[i][j]);
                    wmma::mma_sync(acc[i][j], ah[i], bl[j], acc[i][j]);
                    wmma::mma_sync(acc[i][j], al[i], bh[j], acc[i][j]);
                }
        }
        __syncthreads();
    }

#pragma unroll
    for (int i = 0; i < 2; i++)
#pragma unroll
        for (int j = 0; j < 2; j++) {
            float* cp = g_pi + ((size_t)d * (NB * NT) + mBase + wm * 32 + i * 16) * NG
                             + nBase + wn * 32 + j * 16;
            wmma::store_matrix_sync(cp, acc[i][j], NG, wmma::mem_row_major);
        }
}

// ---------------- persistent per-layer recurrence kernel -----------------------
// 512 blocks x 256 threads, all co-resident (<=64 regs via launch_bounds).
// Per timestep: gates phase (all blocks; 2 cells/warp; c kept in registers)
//   -> grid barrier -> proj phase (blocks 0..127; warp = 1 output, full K)
//   -> grid barrier.
__global__ void __launch_bounds__(256, 4)
layer_recurrence_kernel(const float* __restrict__ Ws_l,   // (2, 16384, 512)
                        const float* __restrict__ bs_l,   // (2, 16384)
                        const float* __restrict__ Wp_l,   // (2, 512, 4096)
                        const int*   __restrict__ mask)
{
    const int blk = blockIdx.x;
    const int tid = threadIdx.x;
    const int w = tid >> 5, lane = tid & 31;

    // gates assignment: dir + two cells per warp
    const int gd = blk >> 8;                       // 0..1
    const int j0 = (blk & 255) * 16 + w * 2;       // cell pair base
    const int j1 = j0 + 1;
    const float* wb  = Ws_l + (size_t)gd * NG * ND;
    const float* bsd = bs_l + (size_t)gd * NG;

    // proj assignment (blocks 0..127): dir + 8 outputs (one per warp)
    const int pd  = blk >> 6;                      // valid when blk < 128
    const int pio = (blk & 63) * 8 + w;

    __shared__ float sh[NB * NH];                  // h for dir gd (8 KB)

    // zero h (16 blocks cover 4096 floats), c lives in registers
    {
        int zi = blk * 256 + tid;
        if (zi < 2 * NB * NH) g_h[zi] = 0.0f;
    }
    float c0[4] = {0.f, 0.f, 0.f, 0.f};   // meaningful in lanes 0..3 (b = lane)
    float c1[4] = {0.f, 0.f, 0.f, 0.f};
    grid_barrier();

    for (int t = 0; t < NT; t++) {
        const int tdg = gd ? (NT - 1 - t) : t;

        // ---- gates phase ----
        {
            const float* hsrc = g_h + (size_t)gd * NB * NH;
            for (int i = tid; i < NB * NH; i += 256) sh[i] = hsrc[i];
            __syncthreads();

            float a0[4][4], a1[4][4];
#pragma unroll
            for (int q = 0; q < 4; q++)
#pragma unroll
                for (int b = 0; b < 4; b++) { a0[q][b] = 0.f; a1[q][b] = 0.f; }

#pragma unroll
            for (int it = 0; it < 4; it++) {
                const int k = it * 128 + lane * 4;
                float4 hv0 = *(const float4*)&sh[0 * NH + k];
                float4 hv1 = *(const float4*)&sh[1 * NH + k];
                float4 hv2 = *(const float4*)&sh[2 * NH + k];
                float4 hv3 = *(const float4*)&sh[3 * NH + k];
#pragma unroll
                for (int q = 0; q < 4; q++) {
                    float4 w0 = *(const float4*)&wb[(size_t)(q * NC + j0) * ND + k];
                    float4 w1 = *(const float4*)&wb[(size_t)(q * NC + j1) * ND + k];
                    a0[q][0] += dot4(w0, hv0); a0[q][1] += dot4(w0, hv1);
                    a0[q][2] += dot4(w0, hv2); a0[q][3] += dot4(w0, hv3);
                    a1[q][0] += dot4(w1, hv0); a1[q][1] += dot4(w1, hv1);
                    a1[q][2] += dot4(w1, hv2); a1[q][3] += dot4(w1, hv3);
                }
            }
#pragma unroll
            for (int off = 16; off > 0; off >>= 1)
#pragma unroll
                for (int q = 0; q < 4; q++)
#pragma unroll
                    for (int b = 0; b < 4; b++) {
                        a0[q][b] += __shfl_xor_sync(0xffffffffu, a0[q][b], off);
                        a1[q][b] += __shfl_xor_sync(0xffffffffu, a1[q][b], off);
                    }

            if (lane < 4) {
                const int b = lane;
                const int mv = mask[b * NT + tdg];
                const float* pib = g_pi + (((size_t)gd * NB + b) * NT + tdg) * NG;
                // cell j0
                {
                    float gi = a0[0][b] + __ldcs(&pib[0 * NC + j0]) + bsd[0 * NC + j0];
                    float gf = a0[1][b] + __ldcs(&pib[1 * NC + j0]) + bsd[1 * NC + j0];
                    float gg = a0[2][b] + __ldcs(&pib[2 * NC + j0]) + bsd[2 * NC + j0];
                    float go = a0[3][b] + __ldcs(&pib[3 * NC + j0]) + bsd[3 * NC + j0];
                    float cn = clip3(sigmoidf_(gi) * tanhf(gg) + sigmoidf_(gf) * c0[b]);
                    if (mv != 0) c0[b] = cn;
                    g_s[((size_t)gd * NB + b) * NC + j0] = sigmoidf_(go) * tanhf(cn);
                }
                // cell j1
                {
                    float gi = a1[0][b] + __ldcs(&pib[0 * NC + j1]) + bsd[0 * NC + j1];
                    float gf = a1[1][b] + __ldcs(&pib[1 * NC + j1]) + bsd[1 * NC + j1];
                    float gg = a1[2][b] + __ldcs(&pib[2 * NC + j1]) + bsd[2 * NC + j1];
                    float go = a1[3][b] + __ldcs(&pib[3 * NC + j1]) + bsd[3 * NC + j1];
                    float cn = clip3(sigmoidf_(gi) * tanhf(gg) + sigmoidf_(gf) * c1[b]);
                    if (mv != 0) c1[b] = cn;
                    g_s[((size_t)gd * NB + b) * NC + j1] = sigmoidf_(go) * tanhf(cn);
                }
            }
        }
        grid_barrier();   // s visible to proj blocks

        // ---- proj phase (blocks 0..127) ----
        if (blk < 128) {
            const int tdp = pd ? (NT - 1 - t) : t;
            const float* wrow  = Wp_l + ((size_t)pd * NH + pio) * NC;
            const float* sbase = g_s + (size_t)pd * NB * NC;

            float acc[4] = {0.f, 0.f, 0.f, 0.f};
#pragma unroll
            for (int it = 0; it < 32; it++) {
                const int k = it * 128 + lane * 4;
                float4 wv = *(const float4*)&wrow[k];
                acc[0] += dot4(wv, *(const float4*)&sbase[0 * NC + k]);
                acc[1] += dot4(wv, *(const float4*)&sbase[1 * NC + k]);
                acc[2] += dot4(wv, *(const float4*)&sbase[2 * NC + k]);
                acc[3] += dot4(wv, *(const float4*)&sbase[3 * NC + k]);
            }
#pragma unroll
            for (int off = 16; off > 0; off >>= 1)
#pragma unroll
                for (int b = 0; b < 4; b++)
                    acc[b] += __shfl_xor_sync(0xffffffffu, acc[b], off);

            if (lane < 4) {
                const int b = lane;
                float v = clip3(acc[b]);
                const size_t yi = (((size_t)pd * NB + b) * NT + tdp) * NH + pio;
                if (mask[b * NT + tdp] != 0) {
                    g_h[((size_t)pd * NB + b) * NH + pio] = v;
                    g_y[yi] = v;
                } else {
                    g_y[yi] = 0.0f;
                }
            }
        }
        grid_barrier();   // h visible to next gates phase
    }
}

// ---------------- finalize layer: skip-add, write output, feed next layer ------
__global__ void __launch_bounds__(512)
finalize_kernel(float* __restrict__ out, int l)
{
    const int idx = blockIdx.x * blockDim.x + threadIdx.x;   // 0 .. 262143
    const int i  = idx & (NH - 1);
    const int tt = (idx >> 9) & (NT - 1);
    const int b  = (idx >> 15) & (NB - 1);
    const int d  = idx >> 17;
    float z = g_y[idx] + (l ? g_x[idx] : 0.0f);
    g_x[idx] = z;
    out[(((size_t)l * NB + b) * NT + tt) * (2 * NH) + d * NH + i] = z;
}

// ---------------- launcher ----------------
extern "C" void kernel_launch(void* const* d_in, const int* in_sizes, int n_in,
                              void* d_out, int out_size)
{
    const float* inputs = (const float*)d_in[0];   // (4,64,512)
    const int*   mask   = (const int*)  d_in[1];   // (4,64)
    const float* Wi     = (const float*)d_in[2];   // (2,2,16384,512)
    const float* Ws     = (const float*)d_in[3];   // (2,2,16384,512)
    const float* bs     = (const float*)d_in[4];   // (2,2,16384)
    const float* Wp     = (const float*)d_in[5];   // (2,2,512,4096)
    float* out = (float*)d_out;                    // (2,4,64,1024)

    for (int l = 0; l < NL; l++) {
        const float* Wi_l = Wi + (size_t)l * 2 * NG * ND;
        const float* Ws_l = Ws + (size_t)l * 2 * NG * ND;
        const float* bs_l = bs + (size_t)l * 2 * NG;
        const float* Wp_l = Wp + (size_t)l * 2 * NH * NC;

        dim3 gp(NG / 64, (NB * NT) / 128, 2);
        pi_kernel<<<gp, 256>>>(inputs, Wi_l, l);

        layer_recurrence_kernel<<<NBLK, 256>>>(Ws_l, bs_l, Wp_l, mask);

        finalize_kernel<<<512, 512>>>(out, l);
    }
}

// round 7
// speedup vs baseline: 1.0265x; 1.0265x over previous
#include <cuda_runtime.h>
#include <cuda_bf16.h>
#include <mma.h>
#include <math.h>

using namespace nvcuda;

// ---------------- problem constants ----------------
#define NL 2          // layers
#define NB 4          // batch
#define NT 64         // time
#define ND 512        // input dim
#define NH 512        // hidden/proj dim
#define NC 4096       // cell dim
#define NG (4*NC)     // 16384 gate rows per dir
#define CLIPV 3.0f
#define NBLK 512      // persistent grid (148*4 = 592 co-resident capacity)
#define SH_LD 520     // padded h row (floats) -> conflict-free LDS.128 across b-groups

// ---------------- device scratch (static allocation: allowed) ----------------
__device__ __align__(16) float g_pi[(size_t)2 * NB * NT * NG];   // [dir][b][t][g]  32 MiB
__device__ __align__(16) float g_x [(size_t)2 * NB * NT * NH];   // layer input
__device__ __align__(16) float g_y [(size_t)2 * NB * NT * NH];   // layer raw out
__device__ __align__(16) float g_s [(size_t)2 * NB * NC];        // sigma(o)*tanh(c_new)
__device__ __align__(16) float g_h [(size_t)2 * NB * NH];        // hidden state

// software grid barrier (zero-init; counter self-resets, epoch monotonic)
__device__ unsigned g_bar_cnt = 0;
__device__ volatile unsigned g_bar_epoch = 0;

__device__ __forceinline__ void grid_barrier() {
    __syncthreads();
    if (threadIdx.x == 0) {
        unsigned e = g_bar_epoch;
        __threadfence();
        if (atomicAdd(&g_bar_cnt, 1u) == NBLK - 1u) {
            g_bar_cnt = 0;
            __threadfence();
            g_bar_epoch = e + 1u;
        } else {
            while (g_bar_epoch == e) {}
            __threadfence();
        }
    }
    __syncthreads();
}

__device__ __forceinline__ float dot4(float4 a, float4 b) {
    return a.x*b.x + a.y*b.y + a.z*b.z + a.w*b.w;
}
__device__ __forceinline__ float sigmoidf_(float x) { return 1.0f / (1.0f + expf(-x)); }
__device__ __forceinline__ float clip3(float x)     { return fminf(CLIPV, fmaxf(-CLIPV, x)); }
__device__ __forceinline__ float4 ldcg4(const float* p) {
    return __ldcg((const float4*)p);
}

// ---------------- pi GEMM: pi[d][m][n] = A[m,:] . Wi[n,:]  (split-bf16, 3 MMAs) ----
__global__ void __launch_bounds__(256)
pi_kernel(const float* __restrict__ x0, const float* __restrict__ Wi_l, int l)
{
    const int d = blockIdx.z;
    const float* A  = l ? (g_x + (size_t)d * (NB * NT * NH)) : x0;
    const float* Bg = Wi_l + (size_t)d * NG * ND;
    const int mBase = blockIdx.y * 128;
    const int nBase = blockIdx.x * 64;

    __shared__ __nv_bfloat16 As[2][128][40];
    __shared__ __nv_bfloat16 Bs[2][64][40];

    wmma::fragment<wmma::accumulator, 16, 16, 16, float> acc[2][2];
#pragma unroll
    for (int i = 0; i < 2; i++)
#pragma unroll
        for (int j = 0; j < 2; j++) wmma::fill_fragment(acc[i][j], 0.0f);

    const int w  = threadIdx.x >> 5;
    const int wm = w >> 1;
    const int wn = w & 1;

    for (int kk = 0; kk < 16; kk++) {
        const int k0 = kk * 32;
#pragma unroll
        for (int rpt = 0; rpt < 4; rpt++) {
            int id = threadIdx.x + rpt * 256;
            int r = id >> 3, c = (id & 7) << 2;
            float4 v = *(const float4*)(A + (size_t)(mBase + r) * ND + k0 + c);
            float vs[4] = {v.x, v.y, v.z, v.w};
#pragma unroll
            for (int q = 0; q < 4; q++) {
                __nv_bfloat16 hi = __float2bfloat16(vs[q]);
                As[0][r][c + q] = hi;
                As[1][r][c + q] = __float2bfloat16(vs[q] - __bfloat162float(hi));
            }
        }
#pragma unroll
        for (int rpt = 0; rpt < 2; rpt++) {
            int id = threadIdx.x + rpt * 256;
            int r = id >> 3, c = (id & 7) << 2;
            float4 v = *(const float4*)(Bg + (size_t)(nBase + r) * ND + k0 + c);
            float vs[4] = {v.x, v.y, v.z, v.w};
#pragma unroll
            for (int q = 0; q < 4; q++) {
                __nv_bfloat16 hi = __float2bfloat16(vs[q]);
                Bs[0][r][c + q] = hi;
                Bs[1][r][c + q] = __float2bfloat16(vs[q] - __bfloat162float(hi));
            }
        }
        __syncthreads();

#pragma unroll
        for (int ks = 0; ks < 2; ks++) {
            wmma::fragment<wmma::matrix_a, 16, 16, 16, __nv_bfloat16, wmma::row_major> ah[2], al[2];
            wmma::fragment<wmma::matrix_b, 16, 16, 16, __nv_bfloat16, wmma::col_major> bh[2], bl[2];
#pragma unroll
            for (int i = 0; i < 2; i++) {
                wmma::load_matrix_sync(ah[i], &As[0][wm * 32 + i * 16][ks * 16], 40);
                wmma::load_matrix_sync(al[i], &As[1][wm * 32 + i * 16][ks * 16], 40);
            }
#pragma unroll
            for (int j = 0; j < 2; j++) {
                wmma::load_matrix_sync(bh[j], &Bs[0][wn * 32 + j * 16][ks * 16], 40);
                wmma::load_matrix_sync(bl[j], &Bs[1][wn * 32 + j * 16][ks * 16], 40);
            }
#pragma unroll
            for (int i = 0; i < 2; i++)
#pragma unroll
                for (int j = 0; j < 2; j++) {
                    wmma::mma_sync(acc[i][j], ah[i], bh[j], acc[i][j]);
                    wmma::mma_sync(acc[i][j], ah[i], bl[j], acc[i][j]);
                    wmma::mma_sync(acc[i][j], al[i], bh[j], acc[i][j]);
                }
        }
        __syncthreads();
    }

#pragma unroll
    for (int i = 0; i < 2; i++)
#pragma unroll
        for (int j = 0; j < 2; j++) {
            float* cp = g_pi + ((size_t)d * (NB * NT) + mBase + wm * 32 + i * 16) * NG
                             + nBase + wn * 32 + j * 16;
            wmma::store_matrix_sync(cp, acc[i][j], NG, wmma::mem_row_major);
        }
}

// ---------------- persistent per-layer recurrence kernel -----------------------
// 512 blocks x 256 threads, all co-resident. Lane layout in gates phase:
// b = lane>>3 (batch), kg = lane&7 (k-slice). acc[2 cells][4 gates] = 8 regs.
__global__ void __launch_bounds__(256, 4)
layer_recurrence_kernel(const float* __restrict__ Ws_l,   // (2, 16384, 512)
                        const float* __restrict__ bs_l,   // (2, 16384)
                        const float* __restrict__ Wp_l,   // (2, 512, 4096)
                        const int*   __restrict__ mask)
{
    const int blk = blockIdx.x;
    const int tid = threadIdx.x;
    const int w = tid >> 5, lane = tid & 31;

    // gates assignment: dir + two cells per warp
    const int gd = blk >> 8;                       // 0..1
    const int j0 = (blk & 255) * 16 + w * 2;       // cell pair base
    const int j1 = j0 + 1;
    const int bb = lane >> 3;                      // batch handled by this lane
    const int kg = lane & 7;                       // k-slice within batch group
    const bool tail = (kg == 0);
    const float* wb = Ws_l + (size_t)gd * NG * ND;

    // bias in registers (constant over time)
    float bi0[4], bi1[4];
#pragma unroll
    for (int q = 0; q < 4; q++) {
        bi0[q] = __ldg(&bs_l[(size_t)gd * NG + q * NC + j0]);
        bi1[q] = __ldg(&bs_l[(size_t)gd * NG + q * NC + j1]);
    }

    // proj assignment (blocks 0..127): dir + 8 outputs (one per warp)
    const int pd  = blk >> 6;
    const int pio = (blk & 63) * 8 + w;

    __shared__ float sh[NB * SH_LD];               // padded h (conflict-free)

    // zero h; c lives in registers (valid in tail lanes, batch bb)
    {
        int zi = blk * 256 + tid;
        if (zi < 2 * NB * NH) g_h[zi] = 0.0f;
    }
    float c0 = 0.0f, c1 = 0.0f;
    grid_barrier();

    for (int t = 0; t < NT; t++) {
        const int tdg = gd ? (NT - 1 - t) : t;

        // ---- stage h (padded) ----
        {
            const float* hsrc = g_h + (size_t)gd * NB * NH;
            for (int i = tid; i < NB * NH; i += 256)
                sh[(i >> 9) * SH_LD + (i & 511)] = hsrc[i];
        }
        __syncthreads();

        // ---- gates: acc[cell][gate], one batch per lane ----
        float acc[2][4];
#pragma unroll
        for (int cc = 0; cc < 2; cc++)
#pragma unroll
            for (int q = 0; q < 4; q++) acc[cc][q] = 0.0f;

        const float* hrow = &sh[bb * SH_LD + kg * 4];
#pragma unroll 4
        for (int it = 0; it < 16; it++) {
            float4 hv = *(const float4*)&hrow[it * 32];
            const int koff = it * 32 + kg * 4;
#pragma unroll
            for (int q = 0; q < 4; q++) {
                float4 w0 = ldcg4(wb + (size_t)(q * NC + j0) * ND + koff);
                float4 w1 = ldcg4(wb + (size_t)(q * NC + j1) * ND + koff);
                acc[0][q] += dot4(w0, hv);
                acc[1][q] += dot4(w1, hv);
            }
        }
        // reduce over the 8 lanes of each batch group (xor 1,2,4)
#pragma unroll
        for (int off = 1; off < 8; off <<= 1)
#pragma unroll
            for (int cc = 0; cc < 2; cc++)
#pragma unroll
                for (int q = 0; q < 4; q++)
                    acc[cc][q] += __shfl_xor_sync(0xffffffffu, acc[cc][q], off);

        if (tail) {
            const int b = bb;
            const int mv = mask[b * NT + tdg];
            const float* pib = g_pi + (((size_t)gd * NB + b) * NT + tdg) * NG;
            // cell j0
            {
                float gi = acc[0][0] + __ldcs(&pib[0 * NC + j0]) + bi0[0];
                float gf = acc[0][1] + __ldcs(&pib[1 * NC + j0]) + bi0[1];
                float gg = acc[0][2] + __ldcs(&pib[2 * NC + j0]) + bi0[2];
                float go = acc[0][3] + __ldcs(&pib[3 * NC + j0]) + bi0[3];
                float cn = clip3(sigmoidf_(gi) * tanhf(gg) + sigmoidf_(gf) * c0);
                if (mv != 0) c0 = cn;
                g_s[((size_t)gd * NB + b) * NC + j0] = sigmoidf_(go) * tanhf(cn);
            }
            // cell j1
            {
                float gi = acc[1][0] + __ldcs(&pib[0 * NC + j1]) + bi1[0];
                float gf = acc[1][1] + __ldcs(&pib[1 * NC + j1]) + bi1[1];
                float gg = acc[1][2] + __ldcs(&pib[2 * NC + j1]) + bi1[2];
                float go = acc[1][3] + __ldcs(&pib[3 * NC + j1]) + bi1[3];
                float cn = clip3(sigmoidf_(gi) * tanhf(gg) + sigmoidf_(gf) * c1);
                if (mv != 0) c1 = cn;
                g_s[((size_t)gd * NB + b) * NC + j1] = sigmoidf_(go) * tanhf(cn);
            }
        }
        grid_barrier();   // s visible to proj blocks

        // ---- proj phase (blocks 0..127): warp = one output, full K ----
        if (blk < 128) {
            const int tdp = pd ? (NT - 1 - t) : t;
            const float* wrow  = Wp_l + ((size_t)pd * NH + pio) * NC;
            const float* sbase = g_s + (size_t)pd * NB * NC;

            float pa[4] = {0.f, 0.f, 0.f, 0.f};
#pragma unroll 8
            for (int it = 0; it < 32; it++) {
                const int k = it * 128 + lane * 4;
                float4 wv = ldcg4(wrow + k);   // Wp: stream via L2 only
                // s: default-cached loads -> L1 serves the 8-warp reuse
                pa[0] += dot4(wv, *(const float4*)&sbase[0 * NC + k]);
                pa[1] += dot4(wv, *(const float4*)&sbase[1 * NC + k]);
                pa[2] += dot4(wv, *(const float4*)&sbase[2 * NC + k]);
                pa[3] += dot4(wv, *(const float4*)&sbase[3 * NC + k]);
            }
#pragma unroll
            for (int off = 16; off > 0; off >>= 1)
#pragma unroll
                for (int b = 0; b < 4; b++)
                    pa[b] += __shfl_xor_sync(0xffffffffu, pa[b], off);

            if (lane < 4) {
                const int b = lane;
                float v = clip3(pa[b]);
                const size_t yi = (((size_t)pd * NB + b) * NT + tdp) * NH + pio;
                if (mask[b * NT + tdp] != 0) {
                    g_h[((size_t)pd * NB + b) * NH + pio] = v;
                    g_y[yi] = v;
                } else {
                    g_y[yi] = 0.0f;
                }
            }
        }
        grid_barrier();   // h visible to next gates phase
    }
}

// ---------------- finalize layer: skip-add, write output, feed next layer ------
__global__ void __launch_bounds__(512)
finalize_kernel(float* __restrict__ out, int l)
{
    const int idx = blockIdx.x * blockDim.x + threadIdx.x;   // 0 .. 262143
    const int i  = idx & (NH - 1);
    const int tt = (idx >> 9) & (NT - 1);
    const int b  = (idx >> 15) & (NB - 1);
    const int d  = idx >> 17;
    float z = g_y[idx] + (l ? g_x[idx] : 0.0f);
    g_x[idx] = z;
    out[(((size_t)l * NB + b) * NT + tt) * (2 * NH) + d * NH + i] = z;
}

// ---------------- launcher ----------------
extern "C" void kernel_launch(void* const* d_in, const int* in_sizes, int n_in,
                              void* d_out, int out_size)
{
    const float* inputs = (const float*)d_in[0];   // (4,64,512)
    const int*   mask   = (const int*)  d_in[1];   // (4,64)
    const float* Wi     = (const float*)d_in[2];   // (2,2,16384,512)
    const float* Ws     = (const float*)d_in[3];   // (2,2,16384,512)
    const float* bs     = (const float*)d_in[4];   // (2,2,16384)
    const float* Wp     = (const float*)d_in[5];   // (2,2,512,4096)
    float* out = (float*)d_out;                    // (2,4,64,1024)

    for (int l = 0; l < NL; l++) {
        const float* Wi_l = Wi + (size_t)l * 2 * NG * ND;
        const float* Ws_l = Ws + (size_t)l * 2 * NG * ND;
        const float* bs_l = bs + (size_t)l * 2 * NG;
        const float* Wp_l = Wp + (size_t)l * 2 * NH * NC;

        dim3 gp(NG / 64, (NB * NT) / 128, 2);
        pi_kernel<<<gp, 256>>>(inputs, Wi_l, l);

        layer_recurrence_kernel<<<NBLK, 256>>>(Ws_l, bs_l, Wp_l, mask);

        finalize_kernel<<<512, 512>>>(out, l);
    }
}

// round 8
// speedup vs baseline: 1.2870x; 1.2538x over previous
#include <cuda_runtime.h>
#include <cuda_bf16.h>
#include <mma.h>
#include <math.h>

using namespace nvcuda;

// ---------------- problem constants ----------------
#define NL 2          // layers
#define NB 4          // batch
#define NT 64         // time
#define ND 512        // input dim
#define NH 512        // hidden/proj dim
#define NC 4096       // cell dim
#define NG (4*NC)     // 16384 gate rows per dir
#define CLIPV 3.0f

// ---------------- device scratch (static allocation: allowed) ----------------
__device__ __align__(16) float g_pi[(size_t)2 * NB * NT * NG];   // [dir][b][t][g]  32 MiB
__device__ __align__(16) float g_x [(size_t)2 * NB * NT * NH];   // layer input
__device__ __align__(16) float g_y [(size_t)2 * NB * NT * NH];   // layer raw out
__device__ __align__(16) float g_s [(size_t)2 * NB * NC];        // sigma(o)*tanh(c_new)
__device__ __align__(16) float g_c [(size_t)2 * NB * NC];        // cell state
// h accumulators (proj atomicAdd target), parity by t; zero-init, re-zeroed in steady state
__device__ __align__(16) float g_hacc[2][2 * NB * NH];
// finalized h (clip+mask applied), parity by t
__device__ __align__(16) float g_hfin[2][2 * NB * NH];

__device__ __forceinline__ float dot4(float4 a, float4 b) {
    return a.x*b.x + a.y*b.y + a.z*b.z + a.w*b.w;
}
__device__ __forceinline__ float sigmoidf_(float x) { return 1.0f / (1.0f + expf(-x)); }
__device__ __forceinline__ float clip3(float x)     { return fminf(CLIPV, fmaxf(-CLIPV, x)); }

// ---------------- init: zero cell state (reference resets per layer/direction) --
__global__ void init_state_kernel() {
    int idx = blockIdx.x * blockDim.x + threadIdx.x;
    if (idx < 2 * NB * NC) g_c[idx] = 0.0f;
}

// ---------------- pi GEMM: pi[d][m][n] = A[m,:] . Wi[n,:]  (split-bf16, 3 MMAs) ----
__global__ void __launch_bounds__(256)
pi_kernel(const float* __restrict__ x0, const float* __restrict__ Wi_l, int l)
{
    const int d = blockIdx.z;
    const float* A  = l ? (g_x + (size_t)d * (NB * NT * NH)) : x0;
    const float* Bg = Wi_l + (size_t)d * NG * ND;
    const int mBase = blockIdx.y * 128;
    const int nBase = blockIdx.x * 64;

    __shared__ __nv_bfloat16 As[2][128][40];
    __shared__ __nv_bfloat16 Bs[2][64][40];

    wmma::fragment<wmma::accumulator, 16, 16, 16, float> acc[2][2];
#pragma unroll
    for (int i = 0; i < 2; i++)
#pragma unroll
        for (int j = 0; j < 2; j++) wmma::fill_fragment(acc[i][j], 0.0f);

    const int w  = threadIdx.x >> 5;
    const int wm = w >> 1;
    const int wn = w & 1;

    for (int kk = 0; kk < 16; kk++) {
        const int k0 = kk * 32;
#pragma unroll
        for (int rpt = 0; rpt < 4; rpt++) {
            int id = threadIdx.x + rpt * 256;
            int r = id >> 3, c = (id & 7) << 2;
            float4 v = *(const float4*)(A + (size_t)(mBase + r) * ND + k0 + c);
            float vs[4] = {v.x, v.y, v.z, v.w};
#pragma unroll
            for (int q = 0; q < 4; q++) {
                __nv_bfloat16 hi = __float2bfloat16(vs[q]);
                As[0][r][c + q] = hi;
                As[1][r][c + q] = __float2bfloat16(vs[q] - __bfloat162float(hi));
            }
        }
#pragma unroll
        for (int rpt = 0; rpt < 2; rpt++) {
            int id = threadIdx.x + rpt * 256;
            int r = id >> 3, c = (id & 7) << 2;
            float4 v = *(const float4*)(Bg + (size_t)(nBase + r) * ND + k0 + c);
            float vs[4] = {v.x, v.y, v.z, v.w};
#pragma unroll
            for (int q = 0; q < 4; q++) {
                __nv_bfloat16 hi = __float2bfloat16(vs[q]);
                Bs[0][r][c + q] = hi;
                Bs[1][r][c + q] = __float2bfloat16(vs[q] - __bfloat162float(hi));
            }
        }
        __syncthreads();

#pragma unroll
        for (int ks = 0; ks < 2; ks++) {
            wmma::fragment<wmma::matrix_a, 16, 16, 16, __nv_bfloat16, wmma::row_major> ah[2], al[2];
            wmma::fragment<wmma::matrix_b, 16, 16, 16, __nv_bfloat16, wmma::col_major> bh[2], bl[2];
#pragma unroll
            for (int i = 0; i < 2; i++) {
                wmma::load_matrix_sync(ah[i], &As[0][wm * 32 + i * 16][ks * 16], 40);
                wmma::load_matrix_sync(al[i], &As[1][wm * 32 + i * 16][ks * 16], 40);
            }
#pragma unroll
            for (int j = 0; j < 2; j++) {
                wmma::load_matrix_sync(bh[j], &Bs[0][wn * 32 + j * 16][ks * 16], 40);
                wmma::load_matrix_sync(bl[j], &Bs[1][wn * 32 + j * 16][ks * 16], 40);
            }
#pragma unroll
            for (int i = 0; i < 2; i++)
#pragma unroll
                for (int j = 0; j < 2; j++) {
                    wmma::mma_sync(acc[i][j], ah[i], bh[j], acc[i][j]);
                    wmma::mma_sync(acc[i][j], ah[i], bl[j], acc[i][j]);
                    wmma::mma_sync(acc[i][j], al[i], bh[j], acc[i][j]);
                }
        }
        __syncthreads();
    }

#pragma unroll
    for (int i = 0; i < 2; i++)
#pragma unroll
        for (int j = 0; j < 2; j++) {
            float* cp = g_pi + ((size_t)d * (NB * NT) + mBase + wm * 32 + i * 16) * NG
                             + nBase + wn * 32 + j * 16;
            wmma::store_matrix_sync(cp, acc[i][j], NG, wmma::mem_row_major);
        }
}

// ---------------- step 1: finalize h(t-1) from hacc, then gates + cell update ---
// grid 1024 x 256 (R4 layout: block -> (dir, 8 cells), warp -> cell j).
// Staging computes h(t-1) = mask ? clip(hacc[(t-1)&1]) : h(t-2); one designated
// block per dir also persists g_hfin[(t-1)&1] and emits y(t-1).
__global__ void __launch_bounds__(256)
step_gates_kernel(const float* __restrict__ Ws_l,   // (2, 16384, 512)
                  const float* __restrict__ bs_l,   // (2, 16384)
                  const int*   __restrict__ mask, int t)
{
    __shared__ float sh[NB * NH];   // h(t-1) for this dir: 8 KB
    const int blk = blockIdx.x;
    const int d  = blk >> 9;
    const int cb = (blk & 511) * 8;
    const int td = d ? (NT - 1 - t) : t;
    const int tid = threadIdx.x;

    // ---- stage h(t-1) ----
    if (t == 0) {
        for (int i = tid; i < NB * NH; i += 256) sh[i] = 0.0f;
    } else {
        const int td1 = d ? (NT - t) : (t - 1);       // time index of step t-1
        const float* hacc = g_hacc[(t - 1) & 1] + (size_t)d * NB * NH;
        const float* hfin = g_hfin[t & 1] + (size_t)d * NB * NH;  // h(t-2)
        const bool wr = ((blk & 511) == 0);
        const int m0 = mask[0 * NT + td1], m1 = mask[1 * NT + td1];
        const int m2 = mask[2 * NT + td1], m3 = mask[3 * NT + td1];
        const bool allv = m0 && m1 && m2 && m3;
        for (int i = tid; i < NB * NH; i += 256) {
            float hraw = hacc[i];
            float hv;
            int b = i >> 9;
            int m = (b == 0) ? m0 : (b == 1) ? m1 : (b == 2) ? m2 : m3;
            if (allv) {
                hv = clip3(hraw);
            } else {
                float hold = (t >= 2) ? hfin[i] : 0.0f;
                hv = m ? clip3(hraw) : hold;
            }
            sh[i] = hv;
            if (wr) {
                g_hfin[(t - 1) & 1][(size_t)d * NB * NH + i] = hv;
                g_y[(((size_t)d * NB + b) * NT + td1) * NH + (i & 511)] = m ? hv : 0.0f;
            }
        }
    }
    __syncthreads();

    // ---- gates (R4 core) ----
    const int w = tid >> 5, lane = tid & 31;
    const int j = cb + w;
    const float* wbase = Ws_l + (size_t)d * NG * ND;

    float acc[4][4];
#pragma unroll
    for (int q = 0; q < 4; q++)
#pragma unroll
        for (int b = 0; b < 4; b++) acc[q][b] = 0.0f;

#pragma unroll
    for (int it = 0; it < 4; it++) {
        const int k = it * 128 + lane * 4;
        float4 hv0 = *(const float4*)&sh[0 * NH + k];
        float4 hv1 = *(const float4*)&sh[1 * NH + k];
        float4 hv2 = *(const float4*)&sh[2 * NH + k];
        float4 hv3 = *(const float4*)&sh[3 * NH + k];
#pragma unroll
        for (int q = 0; q < 4; q++) {
            float4 wv = *(const float4*)&wbase[(size_t)(q * NC + j) * ND + k];
            acc[q][0] += dot4(wv, hv0);
            acc[q][1] += dot4(wv, hv1);
            acc[q][2] += dot4(wv, hv2);
            acc[q][3] += dot4(wv, hv3);
        }
    }
#pragma unroll
    for (int off = 16; off > 0; off >>= 1)
#pragma unroll
        for (int q = 0; q < 4; q++)
#pragma unroll
            for (int b = 0; b < 4; b++)
                acc[q][b] += __shfl_xor_sync(0xffffffffu, acc[q][b], off);

    if (lane < 4) {
        const int b = lane;
        const float* pib = g_pi + (((size_t)d * NB + b) * NT + td) * NG;
        const float* bsd = bs_l + (size_t)d * NG;
        float gi = acc[0][b] + __ldcs(&pib[0 * NC + j]) + bsd[0 * NC + j];
        float gf = acc[1][b] + __ldcs(&pib[1 * NC + j]) + bsd[1 * NC + j];
        float gg = acc[2][b] + __ldcs(&pib[2 * NC + j]) + bsd[2 * NC + j];
        float go = acc[3][b] + __ldcs(&pib[3 * NC + j]) + bsd[3 * NC + j];

        const size_t ci = ((size_t)d * NB + b) * NC + j;
        float cold = g_c[ci];
        float cn = clip3(sigmoidf_(gi) * tanhf(gg) + sigmoidf_(gf) * cold);
        if (mask[b * NT + td] != 0) g_c[ci] = cn;
        g_s[ci] = sigmoidf_(go) * tanhf(cn);
    }
}

// ---------------- step 2: proj partials -> atomicAdd into g_hacc[t&1] ----------
// grid 1024 = 2 d x 64 ig x 8 kc; fire-and-forget (no fence/counter/reduce pass).
// Blocks 0..15 also zero the opposite-parity accumulator for step t+1.
__global__ void __launch_bounds__(256)
step_proj_kernel(const float* __restrict__ Wp_l, int t)
{
    const int blk = blockIdx.x;
    const int d  = blk >> 9;
    const int ig = (blk >> 3) & 63;
    const int kc = blk & 7;

    __shared__ float ss[NB * 512];   // s chunk for this (d, kc)
    const float* sbase = g_s + (size_t)d * NB * NC + kc * 512;
    for (int idx = threadIdx.x; idx < NB * 512; idx += 256) {
        int b = idx >> 9, k = idx & 511;
        ss[idx] = sbase[(size_t)b * NC + k];
    }
    if (blk < 16) g_hacc[(t + 1) & 1][blk * 256 + threadIdx.x] = 0.0f;
    __syncthreads();

    const int w = threadIdx.x >> 5, lane = threadIdx.x & 31;
    const int iOut = ig * 8 + w;
    const float* wrow = Wp_l + ((size_t)d * NH + iOut) * NC + kc * 512;

    float acc[4] = {0.f, 0.f, 0.f, 0.f};
#pragma unroll
    for (int it = 0; it < 4; it++) {
        const int k = it * 128 + lane * 4;
        float4 wv = *(const float4*)&wrow[k];
        acc[0] += dot4(wv, *(const float4*)&ss[0 * 512 + k]);
        acc[1] += dot4(wv, *(const float4*)&ss[1 * 512 + k]);
        acc[2] += dot4(wv, *(const float4*)&ss[2 * 512 + k]);
        acc[3] += dot4(wv, *(const float4*)&ss[3 * 512 + k]);
    }
#pragma unroll
    for (int off = 16; off > 0; off >>= 1)
#pragma unroll
        for (int b = 0; b < 4; b++)
            acc[b] += __shfl_xor_sync(0xffffffffu, acc[b], off);

    if (lane < 4)
        atomicAdd(&g_hacc[t & 1][((size_t)d * NB + lane) * NH + iOut], acc[lane]);
}

// ---------------- finalize layer: emit y(63), skip-add, write output ------------
__global__ void __launch_bounds__(512)
finalize_kernel(float* __restrict__ out, const int* __restrict__ mask, int l)
{
    const int idx = blockIdx.x * blockDim.x + threadIdx.x;   // 0 .. 262143
    const int i  = idx & (NH - 1);
    const int tt = (idx >> 9) & (NT - 1);
    const int b  = (idx >> 15) & (NB - 1);
    const int d  = idx >> 17;

    const int lastT = d ? 0 : (NT - 1);   // time index of step t=63 for this dir
    float yv;
    if (tt == lastT) {
        const int m = mask[b * NT + tt];
        float hraw = g_hacc[(NT - 1) & 1][((size_t)d * NB + b) * NH + i];   // step 63
        float hold = g_hfin[(NT - 2) & 1][((size_t)d * NB + b) * NH + i];   // h(62)
        float hv = m ? clip3(hraw) : hold;
        yv = m ? hv : 0.0f;
    } else {
        yv = g_y[idx];
    }
    float z = yv + (l ? g_x[idx] : 0.0f);
    g_x[idx] = z;
    out[(((size_t)l * NB + b) * NT + tt) * (2 * NH) + d * NH + i] = z;
}

// ---------------- launcher ----------------
extern "C" void kernel_launch(void* const* d_in, const int* in_sizes, int n_in,
                              void* d_out, int out_size)
{
    const float* inputs = (const float*)d_in[0];   // (4,64,512)
    const int*   mask   = (const int*)  d_in[1];   // (4,64)
    const float* Wi     = (const float*)d_in[2];   // (2,2,16384,512)
    const float* Ws     = (const float*)d_in[3];   // (2,2,16384,512)
    const float* bs     = (const float*)d_in[4];   // (2,2,16384)
    const float* Wp     = (const float*)d_in[5];   // (2,2,512,4096)
    float* out = (float*)d_out;                    // (2,4,64,1024)

    for (int l = 0; l < NL; l++) {
        const float* Wi_l = Wi + (size_t)l * 2 * NG * ND;
        const float* Ws_l = Ws + (size_t)l * 2 * NG * ND;
        const float* bs_l = bs + (size_t)l * 2 * NG;
        const float* Wp_l = Wp + (size_t)l * 2 * NH * NC;

        init_state_kernel<<<128, 256>>>();   // per-layer cell-state reset

        dim3 gp(NG / 64, (NB * NT) / 128, 2);
        pi_kernel<<<gp, 256>>>(inputs, Wi_l, l);

        for (int t = 0; t < NT; t++) {
            step_gates_kernel<<<1024, 256>>>(Ws_l, bs_l, mask, t);
            step_proj_kernel<<<1024, 256>>>(Wp_l, t);
        }
        finalize_kernel<<<512, 512>>>(out, mask, l);
    }
}